// round 17
// baseline (speedup 1.0000x reference)
#include <cuda_runtime.h>

// Shapes fixed by the problem: bz=4, C=32, H=W=256, NF=12 focal slices.
#define NF    12
#define BZ    4
#define C_    32
#define HW    65536           // 256*256
#define CHW   (C_ * HW)       // 2,097,152
#define CHW4  (CHW / 4)       // 524,288 = 2^19
#define HW4   (HW / 4)        // 16,384

#define BPB   128             // reduction blocks along the chunk axis (R2-exact)
#define TPB   256
#define CHUNK (CHW4 / BPB)    // 4096 float4 per block (16 iters/thread)

// Scratch (no allocation allowed).
__device__ float    g_part[BZ * NF * BPB];   // 24 KB -> L2-resident for selection
__device__ int      g_sel[2 * BZ];
__device__ unsigned g_ready = 0;  // set by copy's block 0; reset by next reduce

// ---------------------------------------------------------------------------
// Kernel 1: EXACT R2 reduce (best measured: 68.7us @ 81% DRAM, 86 regs) plus
// a one-store prologue that resets the publish flag for graph replays
// (safe: stream-serialized before the consumer kernel).
// grid = (BPB, BZ).
// ---------------------------------------------------------------------------
__global__ __launch_bounds__(TPB, 2) void k_reduce(const float* __restrict__ x,
                                                   const float* __restrict__ xf,
                                                   const float* __restrict__ sal) {
    if (blockIdx.x == 0 && blockIdx.y == 0 && threadIdx.x == 0)
        g_ready = 0;   // replay reset; visible before k_copy starts (stream order)

    const int b    = blockIdx.y;
    const int base = blockIdx.x * CHUNK;

    const float4* __restrict__ xp = (const float4*)(x   + (size_t)b * CHW);
    const float4* __restrict__ sp = (const float4*)(sal + (size_t)b * HW);

    const float4* __restrict__ fp[NF];
#pragma unroll
    for (int f = 0; f < NF; ++f)
        fp[f] = (const float4*)(xf + ((size_t)f * BZ + b) * CHW);

    float acc[NF];
#pragma unroll
    for (int f = 0; f < NF; ++f) acc[f] = 0.f;

    for (int i = threadIdx.x; i < CHUNK; i += TPB) {
        const int v = base + i;
        const float4 a = xp[v];
        const float4 s = sp[v & (HW4 - 1)];       // sal broadcast over channels
        float4 g[NF];
#pragma unroll
        for (int f = 0; f < NF; ++f) g[f] = __ldcs(&fp[f][v]);
#pragma unroll
        for (int f = 0; f < NF; ++f) {
            acc[f] += fabsf(s.x * (a.x - g[f].x));
            acc[f] += fabsf(s.y * (a.y - g[f].y));
            acc[f] += fabsf(s.z * (a.z - g[f].z));
            acc[f] += fabsf(s.w * (a.w - g[f].w));
        }
    }

    // Warp shuffle reduce each of the 12 accumulators, then combine warps.
    const int lane = threadIdx.x & 31;
    const int warp = threadIdx.x >> 5;
#pragma unroll
    for (int f = 0; f < NF; ++f) {
        float v = acc[f];
#pragma unroll
        for (int o = 16; o > 0; o >>= 1)
            v += __shfl_down_sync(0xffffffffu, v, o);
        acc[f] = v;   // valid on lane 0
    }

    __shared__ float sh[TPB / 32][NF];
    if (lane == 0) {
#pragma unroll
        for (int f = 0; f < NF; ++f) sh[warp][f] = acc[f];
    }
    __syncthreads();
    if (threadIdx.x < NF) {
        const int f = threadIdx.x;
        float s = 0.f;
#pragma unroll
        for (int w = 0; w < TPB / 32; ++w) s += sh[w][f];
        g_part[(b * NF + f) * BPB + blockIdx.x] = s;
    }
}

// ---------------------------------------------------------------------------
// Kernel 2: gather-copy with selection fused into block 0 ONLY.
// __launch_bounds__(256, 6) caps registers (~40) so the copy path keeps the
// measured-best occupancy; the once-only selection path may spill (harmless).
// Block 0: parallel partial sums (fixed order, deterministic doubles),
// per-batch 66-pair first-max, publish g_sel, release flag. Others poll ~2us.
// Block chunk = 2048 float4, divides CHW4 -> one output row per block.
// ---------------------------------------------------------------------------
#define CPT 8
__global__ __launch_bounds__(TPB, 6) void k_copy(const float* __restrict__ xf,
                                                 float* __restrict__ out) {
    const int t = threadIdx.x;

    if (blockIdx.x == 0) {
        __shared__ double part4[BZ * NF][4];
        __shared__ double mae[BZ * NF];
        if (t < BZ * NF * 4) {                  // 192 threads
            const int bf = t >> 2;
            const int g  = t & 3;
            const float* __restrict__ row = &g_part[bf * BPB + g * 32];
            double s = 0.0;
#pragma unroll 8
            for (int q = 0; q < 32; ++q)        // batched independent loads
                s += (double)__ldg(&row[q]);
            part4[bf][g] = s;
        }
        __syncthreads();
        if (t < BZ * NF)
            mae[t] = ((part4[t][0] + part4[t][1]) + part4[t][2]) + part4[t][3];
        __syncthreads();
        if (t < BZ) {
            double m[NF];
#pragma unroll
            for (int f = 0; f < NF; ++f) m[f] = mae[t * NF + f];
            double best = -1.0;
            int bi = 0, bj = 0;
            for (int i = 0; i < NF; ++i)
                for (int j = i + 1; j < NF; ++j) {
                    const double d = m[i] - m[j];
                    const double v = d * d;      // 0.5 irrelevant for ordering
                    if (v > best) { best = v; bi = i; bj = j; }
                }
            if (!(best > 0.0)) { bi = 0; bj = 0; }
            g_sel[t]      = bi;
            g_sel[BZ + t] = bj;
        }
        __syncthreads();
        if (t == 0) {
            __threadfence();                     // release g_sel
            *((volatile unsigned*)&g_ready) = 1u;
        }
    } else {
        if (t == 0) {
            while (*((volatile unsigned*)&g_ready) == 0u) __nanosleep(32);
        }
        __syncthreads();
        __threadfence();                         // acquire g_sel
    }

    // ---- streaming copy (R6-proven): batch 8 loads, then 8 stores ----
    const long long q0 = (long long)blockIdx.x * (TPB * CPT);
    const int r     = (int)(q0 >> 19);      // output row 0..7, constant per block
    const int b     = r & (BZ - 1);
    const int which = r >> 2;
    const int f     = __ldcg(&g_sel[which * BZ + b]);

    const float4* __restrict__ src = (const float4*)(xf + ((size_t)f * BZ + b) * CHW);
    float4* __restrict__ dst = (float4*)out;

    const int n0 = (int)(q0 & (CHW4 - 1)) + t;
    float4 v[CPT];
#pragma unroll
    for (int c = 0; c < CPT; ++c) v[c] = __ldcs(&src[n0 + c * TPB]);
#pragma unroll
    for (int c = 0; c < CPT; ++c) dst[q0 + t + c * TPB] = v[c];
}

// ---------------------------------------------------------------------------
extern "C" void kernel_launch(void* const* d_in, const int* in_sizes, int n_in,
                              void* d_out, int out_size) {
    const float* x   = (const float*)d_in[0];   // [4,32,256,256]
    const float* xf  = (const float*)d_in[1];   // [48,32,256,256]
    const float* sal = (const float*)d_in[2];   // [4,1,256,256]
    float*       out = (float*)d_out;           // [8,32,256,256]

    dim3 gridR(BPB, BZ);
    k_reduce<<<gridR, TPB>>>(x, xf, sal);
    const unsigned blocksC = (unsigned)((2LL * BZ * CHW4) / (TPB * CPT)); // 2048
    k_copy<<<blocksC, TPB>>>(xf, out);
}